// round 2
// baseline (speedup 1.0000x reference)
#include <cuda_runtime.h>
#include <math.h>

// ---------------------------------------------------------------------------
// HumanPoseModule: 6D rotations -> global matrices -> local rotations -> axis-angle
// One thread per (b,t) sample. 16 non-trivial joints; 8 ignored joints are zero.
// ---------------------------------------------------------------------------

__device__ __forceinline__ void r6d_to_mat(const float* __restrict__ p, float R[9]) {
    // p: 6 contiguous floats (8-byte aligned). rows of R are b1,b2,b3.
    float2 v0 = __ldg((const float2*)(p + 0));
    float2 v1 = __ldg((const float2*)(p + 2));
    float2 v2 = __ldg((const float2*)(p + 4));
    float a1x = v0.x, a1y = v0.y, a1z = v1.x;
    float a2x = v1.y, a2y = v2.x, a2z = v2.y;

    float n1 = sqrtf(a1x*a1x + a1y*a1y + a1z*a1z);
    float in1 = 1.0f / n1;
    float b1x = a1x*in1, b1y = a1y*in1, b1z = a1z*in1;

    float dt = b1x*a2x + b1y*a2y + b1z*a2z;
    float b2x = a2x - dt*b1x, b2y = a2y - dt*b1y, b2z = a2z - dt*b1z;
    float n2 = sqrtf(b2x*b2x + b2y*b2y + b2z*b2z);
    float in2 = 1.0f / n2;
    b2x *= in2; b2y *= in2; b2z *= in2;

    float b3x = b1y*b2z - b1z*b2y;
    float b3y = b1z*b2x - b1x*b2z;
    float b3z = b1x*b2y - b1y*b2x;

    R[0]=b1x; R[1]=b1y; R[2]=b1z;
    R[3]=b2x; R[4]=b2y; R[5]=b2z;
    R[6]=b3x; R[7]=b3y; R[8]=b3z;
}

// C = A @ B
__device__ __forceinline__ void mat_mul(const float A[9], const float B[9], float C[9]) {
#pragma unroll
    for (int i = 0; i < 3; i++) {
#pragma unroll
        for (int j = 0; j < 3; j++) {
            C[3*i+j] = A[3*i+0]*B[0+j] + A[3*i+1]*B[3+j] + A[3*i+2]*B[6+j];
        }
    }
}

// C = A^T @ B   (local = parent^T @ child)
__device__ __forceinline__ void mat_tmul(const float A[9], const float B[9], float C[9]) {
#pragma unroll
    for (int i = 0; i < 3; i++) {
#pragma unroll
        for (int j = 0; j < 3; j++) {
            C[3*i+j] = A[0+i]*B[0+j] + A[3+i]*B[3+j] + A[6+i]*B[6+j];
        }
    }
}

// matrix -> quaternion -> axis-angle (literal transcription of reference math)
__device__ __forceinline__ void mat_to_aa(const float m[9], float* __restrict__ out) {
    float m00=m[0], m01=m[1], m02=m[2];
    float m10=m[3], m11=m[4], m12=m[5];
    float m20=m[6], m21=m[7], m22=m[8];

    float qa0 = sqrtf(fmaxf(1.0f + m00 + m11 + m22, 0.0f));
    float qa1 = sqrtf(fmaxf(1.0f + m00 - m11 - m22, 0.0f));
    float qa2 = sqrtf(fmaxf(1.0f - m00 + m11 - m22, 0.0f));
    float qa3 = sqrtf(fmaxf(1.0f - m00 - m11 + m22, 0.0f));

    // argmax with first-max semantics (strict >)
    int idx = 0; float best = qa0;
    if (qa1 > best) { best = qa1; idx = 1; }
    if (qa2 > best) { best = qa2; idx = 2; }
    if (qa3 > best) { best = qa3; idx = 3; }

    float c0, c1, c2, c3;
    if (idx == 0)      { c0 = qa0*qa0;  c1 = m21-m12;  c2 = m02-m20;  c3 = m10-m01; }
    else if (idx == 1) { c0 = m21-m12;  c1 = qa1*qa1;  c2 = m10+m01;  c3 = m02+m20; }
    else if (idx == 2) { c0 = m02-m20;  c1 = m10+m01;  c2 = qa2*qa2;  c3 = m12+m21; }
    else               { c0 = m10-m01;  c1 = m20+m02;  c2 = m21+m12;  c3 = qa3*qa3; }

    float denom = 2.0f * fmaxf(best, 0.1f);
    float id = 1.0f / denom;
    float q0 = c0*id, q1 = c1*id, q2 = c2*id, q3 = c3*id;

    float nrm  = sqrtf(q1*q1 + q2*q2 + q3*q3);
    float half = atan2f(nrm, q0);
    float ang  = 2.0f * half;

    float sho;
    if (fabsf(ang) < 1e-6f) sho = 0.5f - ang*ang*(1.0f/48.0f);
    else                    sho = sinf(half) / ang;

    float is = 1.0f / sho;
    out[0] = q1*is; out[1] = q2*is; out[2] = q3*is;
}

__global__ void __launch_bounds__(256)
pose_kernel(const float* __restrict__ glb,   // (BT, 10, 6)
            const float* __restrict__ ori,   // (BT, 6, 6)
            float* __restrict__ out,         // (BT, 24, 3)
            int n)
{
    int i = blockIdx.x * blockDim.x + threadIdx.x;
    if (i >= n) return;

    const float* g  = glb + (size_t)i * 60;
    const float* o6 = ori + (size_t)i * 36;
    float* po = out + (size_t)i * 72;

    // Ignored joints {7,8,10,11,20,21,22,23} -> zero axis-angle.
    // float offsets: 21..26, 30..35, 60..71
#pragma unroll
    for (int k = 21; k < 27; k++) po[k] = 0.0f;
#pragma unroll
    for (int k = 30; k < 36; k++) po[k] = 0.0f;
#pragma unroll
    for (int k = 60; k < 72; k++) po[k] = 0.0f;

    float root[9], Rj[9], F[9], L[9];

    // joint 0: local = full[0] = root
    r6d_to_mat(o6 + 0, root);
    mat_to_aa(root, po + 0);

    // --- chain A: 0 -> 1 -> 4 ---
    float F1[9];
    r6d_to_mat(g + 0, Rj);  mat_mul(root, Rj, F1);
    mat_tmul(root, F1, L);  mat_to_aa(L, po + 3);        // joint 1
    r6d_to_mat(o6 + 6, Rj); mat_mul(root, Rj, F);
    mat_tmul(F1, F, L);     mat_to_aa(L, po + 12);       // joint 4 (parent 1)

    // --- chain B: 0 -> 2 -> 5 ---
    float F2[9];
    r6d_to_mat(g + 6, Rj);   mat_mul(root, Rj, F2);
    mat_tmul(root, F2, L);   mat_to_aa(L, po + 6);       // joint 2
    r6d_to_mat(o6 + 12, Rj); mat_mul(root, Rj, F);
    mat_tmul(F2, F, L);      mat_to_aa(L, po + 15);      // joint 5 (parent 2)

    // --- spine chain: 0 -> 3 -> 6 -> 9 -> {12->15, 13->16->18, 14->17->19} ---
    float F3[9];
    r6d_to_mat(g + 12, Rj);  mat_mul(root, Rj, F3);
    mat_tmul(root, F3, L);   mat_to_aa(L, po + 9);       // joint 3

    float F6[9];
    r6d_to_mat(g + 18, Rj);  mat_mul(root, Rj, F6);
    mat_tmul(F3, F6, L);     mat_to_aa(L, po + 18);      // joint 6 (parent 3)

    float F9[9];
    r6d_to_mat(g + 24, Rj);  mat_mul(root, Rj, F9);
    mat_tmul(F6, F9, L);     mat_to_aa(L, po + 27);      // joint 9 (parent 6)

    float F12[9];
    r6d_to_mat(g + 30, Rj);  mat_mul(root, Rj, F12);
    mat_tmul(F9, F12, L);    mat_to_aa(L, po + 36);      // joint 12 (parent 9)

    float F13[9];
    r6d_to_mat(g + 36, Rj);  mat_mul(root, Rj, F13);
    mat_tmul(F9, F13, L);    mat_to_aa(L, po + 39);      // joint 13 (parent 9)

    float F14[9];
    r6d_to_mat(g + 42, Rj);  mat_mul(root, Rj, F14);
    mat_tmul(F9, F14, L);    mat_to_aa(L, po + 42);      // joint 14 (parent 9)

    // joint 15 (sensor 3, parent 12)
    r6d_to_mat(o6 + 18, Rj); mat_mul(root, Rj, F);
    mat_tmul(F12, F, L);     mat_to_aa(L, po + 45);

    // joint 16 (parent 13) then joint 18 (sensor 4, parent 16)
    float F16[9];
    r6d_to_mat(g + 48, Rj);  mat_mul(root, Rj, F16);
    mat_tmul(F13, F16, L);   mat_to_aa(L, po + 48);
    r6d_to_mat(o6 + 24, Rj); mat_mul(root, Rj, F);
    mat_tmul(F16, F, L);     mat_to_aa(L, po + 54);

    // joint 17 (parent 14) then joint 19 (sensor 5, parent 17)
    float F17[9];
    r6d_to_mat(g + 54, Rj);  mat_mul(root, Rj, F17);
    mat_tmul(F14, F17, L);   mat_to_aa(L, po + 51);
    r6d_to_mat(o6 + 30, Rj); mat_mul(root, Rj, F);
    mat_tmul(F17, F, L);     mat_to_aa(L, po + 57);
}

extern "C" void kernel_launch(void* const* d_in, const int* in_sizes, int n_in,
                              void* d_out, int out_size) {
    // Identify inputs robustly: glb_reduced_6d (BT*60 elems) is larger than
    // orientation_6d (BT*36 elems).
    const float* glb;
    const float* ori;
    if (in_sizes[0] >= in_sizes[1]) {
        glb = (const float*)d_in[0];
        ori = (const float*)d_in[1];
    } else {
        glb = (const float*)d_in[1];
        ori = (const float*)d_in[0];
    }
    int n = out_size / 72;  // BT samples, 24*3 floats each

    const int threads = 256;
    const int blocks = (n + threads - 1) / threads;
    pose_kernel<<<blocks, threads>>>(glb, ori, (float*)d_out, n);
}

// round 3
// speedup vs baseline: 1.4554x; 1.4554x over previous
#include <cuda_runtime.h>
#include <math.h>

// ---------------------------------------------------------------------------
// HumanPoseModule: 6D rotations -> global FK -> local rotations -> axis-angle
// One thread per (b,t) sample. 16 non-trivial joints; 8 ignored joints zero.
// ---------------------------------------------------------------------------

#define FDIV(a,b) __fdividef((a),(b))

// Octant-reduced atan2 for y >= 0 (result in [0, pi]).
// Degree-11 odd minimax for atan(t), t in [0,1]; max err ~2e-8.
__device__ __forceinline__ float fast_atan2_pos(float y, float x) {
    float ax = fabsf(x);
    float mn = fminf(y, ax);
    float mx = fmaxf(y, ax);
    float t  = FDIV(mn, mx);            // mx > 0 always here (|q| ~= 1)
    float t2 = t * t;
    float p = -0.0117212f;
    p = fmaf(p, t2,  0.05265332f);
    p = fmaf(p, t2, -0.11643287f);
    p = fmaf(p, t2,  0.19354346f);
    p = fmaf(p, t2, -0.33262347f);
    p = fmaf(p, t2,  0.99997726f);
    p = p * t;
    float r = (y > ax) ? (1.57079632679f - p) : p;
    if (x < 0.0f) r = 3.14159265359f - r;
    return r;
}

// 6D -> rotation matrix. A16: pointer is 16B aligned (use float4+float2),
// else 8B aligned (float2 + float4 at +2).
template <bool A16>
__device__ __forceinline__ void r6d_to_mat(const float* __restrict__ p, float R[9]) {
    float a1x, a1y, a1z, a2x, a2y, a2z;
    if (A16) {
        float4 v = *(const float4*)(p);
        float2 w = *(const float2*)(p + 4);
        a1x = v.x; a1y = v.y; a1z = v.z; a2x = v.w; a2y = w.x; a2z = w.y;
    } else {
        float2 v = *(const float2*)(p);
        float4 w = *(const float4*)(p + 2);
        a1x = v.x; a1y = v.y; a1z = w.x; a2x = w.y; a2y = w.z; a2z = w.w;
    }

    float in1 = rsqrtf(a1x*a1x + a1y*a1y + a1z*a1z);
    float b1x = a1x*in1, b1y = a1y*in1, b1z = a1z*in1;

    float dt = b1x*a2x + b1y*a2y + b1z*a2z;
    float b2x = a2x - dt*b1x, b2y = a2y - dt*b1y, b2z = a2z - dt*b1z;
    float in2 = rsqrtf(b2x*b2x + b2y*b2y + b2z*b2z);
    b2x *= in2; b2y *= in2; b2z *= in2;

    float b3x = b1y*b2z - b1z*b2y;
    float b3y = b1z*b2x - b1x*b2z;
    float b3z = b1x*b2y - b1y*b2x;

    R[0]=b1x; R[1]=b1y; R[2]=b1z;
    R[3]=b2x; R[4]=b2y; R[5]=b2z;
    R[6]=b3x; R[7]=b3y; R[8]=b3z;
}

// C = A @ B
__device__ __forceinline__ void mat_mul(const float A[9], const float B[9], float C[9]) {
#pragma unroll
    for (int i = 0; i < 3; i++)
#pragma unroll
        for (int j = 0; j < 3; j++)
            C[3*i+j] = A[3*i+0]*B[0+j] + A[3*i+1]*B[3+j] + A[3*i+2]*B[6+j];
}

// C = A^T @ B   (local = parent^T @ child)
__device__ __forceinline__ void mat_tmul(const float A[9], const float B[9], float C[9]) {
#pragma unroll
    for (int i = 0; i < 3; i++)
#pragma unroll
        for (int j = 0; j < 3; j++)
            C[3*i+j] = A[0+i]*B[0+j] + A[3+i]*B[3+j] + A[6+i]*B[6+j];
}

// matrix -> axis-angle (reference-equivalent; sqrt/sinf/div eliminated where
// exact monotonicity / trig identities allow)
__device__ __forceinline__ void mat_to_aa(const float m[9], float* __restrict__ out) {
    float m00=m[0], m01=m[1], m02=m[2];
    float m10=m[3], m11=m[4], m12=m[5];
    float m20=m[6], m21=m[7], m22=m[8];

    // clamped squared q_abs; argmax identical to argmax over sqrt values
    float w0 = fmaxf(1.0f + m00 + m11 + m22, 0.0f);
    float w1 = fmaxf(1.0f + m00 - m11 - m22, 0.0f);
    float w2 = fmaxf(1.0f - m00 + m11 - m22, 0.0f);
    float w3 = fmaxf(1.0f - m00 - m11 + m22, 0.0f);

    int idx = 0; float best = w0;
    if (w1 > best) { best = w1; idx = 1; }
    if (w2 > best) { best = w2; idx = 2; }
    if (w3 > best) { best = w3; idx = 3; }

    float d21 = m21 - m12, d02 = m02 - m20, d10 = m10 - m01;
    float s10 = m10 + m01, s02 = m02 + m20, s21 = m21 + m12;

    float c0, c1, c2, c3;
    if (idx == 0)      { c0 = w0;  c1 = d21; c2 = d02; c3 = d10; }
    else if (idx == 1) { c0 = d21; c1 = w1;  c2 = s10; c3 = s02; }
    else if (idx == 2) { c0 = d02; c1 = s10; c2 = w2;  c3 = s21; }
    else               { c0 = d10; c1 = s02; c2 = s21; c3 = w3;  }

    float qb = sqrtf(best);                  // >= 1 always (traces sum to 4)
    float id = FDIV(0.5f, fmaxf(qb, 0.1f));
    float q0 = c0*id, q1 = c1*id, q2 = c2*id, q3 = c3*id;

    float nrm2 = q1*q1 + q2*q2 + q3*q3;
    float nrm  = sqrtf(nrm2);
    float half = fast_atan2_pos(nrm, q0);
    float ang  = 2.0f * half;

    float scale;
    if (fabsf(ang) < 1e-6f) {
        // sho = 0.5 - ang^2/48 ; out = q/sho
        scale = FDIV(1.0f, 0.5f - ang*ang*(1.0f/48.0f));
    } else {
        // sin(half) = nrm / sqrt(nrm^2 + q0^2)  (exact identity for atan2)
        float len = sqrtf(nrm2 + q0*q0);
        scale = FDIV(ang * len, nrm);
    }
    out[0] = q1*scale; out[1] = q2*scale; out[2] = q3*scale;
}

__global__ void __launch_bounds__(256)
pose_kernel(const float* __restrict__ glb,   // (BT, 10, 6)
            const float* __restrict__ ori,   // (BT, 6, 6)
            float* __restrict__ out,         // (BT, 24, 3)
            int n)
{
    int i = blockIdx.x * blockDim.x + threadIdx.x;
    if (i >= n) return;

    const float* g  = glb + (size_t)i * 60;   // base 240B-aligned pattern
    const float* o6 = ori + (size_t)i * 36;   // base 144B -> 16B aligned
    float* po = out + (size_t)i * 72;         // base 288B -> 16B aligned

    // Ignored joints {7,8,10,11,20,21,22,23} -> zero axis-angle.
    po[21]=0.f; po[22]=0.f; po[23]=0.f; po[24]=0.f; po[25]=0.f; po[26]=0.f;
    *(float2*)(po + 30) = make_float2(0.f, 0.f);          // 120B: 8-aligned
    *(float4*)(po + 32) = make_float4(0.f,0.f,0.f,0.f);   // 128B: 16-aligned
    *(float4*)(po + 60) = make_float4(0.f,0.f,0.f,0.f);   // 240B+288B*i: 16-aligned
    *(float4*)(po + 64) = make_float4(0.f,0.f,0.f,0.f);
    *(float4*)(po + 68) = make_float4(0.f,0.f,0.f,0.f);

    float root[9], Rj[9], F[9], L[9];

    // joint 0: local = root  (ori sensor 0, offset 0 -> 16B aligned)
    r6d_to_mat<true>(o6 + 0, root);
    mat_to_aa(root, po + 0);

    // --- chain A: 0 -> 1 -> 4 ---
    float F1[9];
    r6d_to_mat<true >(g + 0, Rj);   mat_mul(root, Rj, F1);
    mat_tmul(root, F1, L);          mat_to_aa(L, po + 3);    // joint 1
    r6d_to_mat<false>(o6 + 6, Rj);  mat_mul(root, Rj, F);
    mat_tmul(F1, F, L);             mat_to_aa(L, po + 12);   // joint 4

    // --- chain B: 0 -> 2 -> 5 ---
    float F2[9];
    r6d_to_mat<false>(g + 6, Rj);   mat_mul(root, Rj, F2);
    mat_tmul(root, F2, L);          mat_to_aa(L, po + 6);    // joint 2
    r6d_to_mat<true >(o6 + 12, Rj); mat_mul(root, Rj, F);
    mat_tmul(F2, F, L);             mat_to_aa(L, po + 15);   // joint 5

    // --- spine: 0 -> 3 -> 6 -> 9 -> {12->15, 13->16->18, 14->17->19} ---
    float F3[9];
    r6d_to_mat<true >(g + 12, Rj);  mat_mul(root, Rj, F3);
    mat_tmul(root, F3, L);          mat_to_aa(L, po + 9);    // joint 3

    float F6[9];
    r6d_to_mat<false>(g + 18, Rj);  mat_mul(root, Rj, F6);
    mat_tmul(F3, F6, L);            mat_to_aa(L, po + 18);   // joint 6

    float F9[9];
    r6d_to_mat<true >(g + 24, Rj);  mat_mul(root, Rj, F9);
    mat_tmul(F6, F9, L);            mat_to_aa(L, po + 27);   // joint 9

    float F12[9];
    r6d_to_mat<false>(g + 30, Rj);  mat_mul(root, Rj, F12);
    mat_tmul(F9, F12, L);           mat_to_aa(L, po + 36);   // joint 12

    float F13[9];
    r6d_to_mat<true >(g + 36, Rj);  mat_mul(root, Rj, F13);
    mat_tmul(F9, F13, L);           mat_to_aa(L, po + 39);   // joint 13

    float F14[9];
    r6d_to_mat<false>(g + 42, Rj);  mat_mul(root, Rj, F14);
    mat_tmul(F9, F14, L);           mat_to_aa(L, po + 42);   // joint 14

    // joint 15 (sensor 3, parent 12)  ori offset 18 -> 72B: 8-aligned
    r6d_to_mat<false>(o6 + 18, Rj); mat_mul(root, Rj, F);
    mat_tmul(F12, F, L);            mat_to_aa(L, po + 45);

    // joint 16 (parent 13), joint 18 (sensor 4, parent 16)
    float F16[9];
    r6d_to_mat<true >(g + 48, Rj);  mat_mul(root, Rj, F16);
    mat_tmul(F13, F16, L);          mat_to_aa(L, po + 48);
    r6d_to_mat<true >(o6 + 24, Rj); mat_mul(root, Rj, F);
    mat_tmul(F16, F, L);            mat_to_aa(L, po + 54);

    // joint 17 (parent 14), joint 19 (sensor 5, parent 17)
    float F17[9];
    r6d_to_mat<false>(g + 54, Rj);  mat_mul(root, Rj, F17);
    mat_tmul(F14, F17, L);          mat_to_aa(L, po + 51);
    r6d_to_mat<false>(o6 + 30, Rj); mat_mul(root, Rj, F);
    mat_tmul(F17, F, L);            mat_to_aa(L, po + 57);
}

extern "C" void kernel_launch(void* const* d_in, const int* in_sizes, int n_in,
                              void* d_out, int out_size) {
    const float* glb;
    const float* ori;
    if (in_sizes[0] >= in_sizes[1]) {
        glb = (const float*)d_in[0];
        ori = (const float*)d_in[1];
    } else {
        glb = (const float*)d_in[1];
        ori = (const float*)d_in[0];
    }
    int n = out_size / 72;

    const int threads = 256;
    const int blocks = (n + threads - 1) / threads;
    pose_kernel<<<blocks, threads>>>(glb, ori, (float*)d_out, n);
}